// round 11
// baseline (speedup 1.0000x reference)
#include <cuda_runtime.h>
#include <cstdint>

typedef unsigned long long ull;

// ---------------- problem constants ----------------
#define T_STEPS 2048
#define BATCH   64
#define FEAT    13
#define HID     300
#define OUT_MAIN (BATCH*T_STEPS*FEAT)
#define OUT_EMB_OFF OUT_MAIN

// ---------------- encoder config ----------------
#define CLUSTER 8
#define NB      4                 // batch per cluster
#define HC      38                // hidden units per CTA (8*38 = 304)
#define KSPLIT  8
#define TENC    (HC*KSPLIT)       // 304 threads
#define KPS     19                // ull k-pairs per lane (38 floats)
#define ROWF    56                // floats per (chunk,batch) row (pad for banks)
#define CHUNKF  (NB*ROWF)         // 224 floats per chunk
#define CHUNKB  (CHUNKF*4)        // 896 B per chunk
#define EXPB    ((CLUSTER-1)*CHUNKB) // 6272 B expected per step (self-skip)

__device__ float g_hlast[BATCH*HID];
__device__ float g_emb[BATCH*HID];

// ---------------- helpers ----------------
__device__ __forceinline__ float sig_f(float x) {
    return __fdividef(1.f, 1.f + __expf(-x));
}
__device__ __forceinline__ float tanh_f(float x) {
    return 1.f - __fdividef(2.f, __expf(2.f * x) + 1.f);
}
__device__ __forceinline__ unsigned smem_u32(const void* p) {
    unsigned a;
    asm("{ .reg .u64 t; cvta.to.shared.u64 t, %1; cvt.u32.u64 %0, t; }"
        : "=r"(a) : "l"(p));
    return a;
}
__device__ __forceinline__ void cluster_sync_() {
    asm volatile("barrier.cluster.arrive.aligned;" ::: "memory");
    asm volatile("barrier.cluster.wait.aligned;" ::: "memory");
}
__device__ __forceinline__ ull pk2(float lo, float hi) {
    ull r;
    asm("mov.b64 %0, {%1, %2};" : "=l"(r) : "f"(lo), "f"(hi));
    return r;
}
__device__ __forceinline__ void fma2(ull& d, ull a, ull b) {
    asm("fma.rn.f32x2 %0, %1, %2, %0;" : "+l"(d) : "l"(a), "l"(b));
}
__device__ __forceinline__ float upks(ull v) {
    float lo, hi;
    asm("mov.b64 {%0, %1}, %2;" : "=f"(lo), "=f"(hi) : "l"(v));
    return lo + hi;
}
__device__ __forceinline__ unsigned mapa_(unsigned a, int rank) {
    unsigned r;
    asm("mapa.shared::cluster.u32 %0, %1, %2;" : "=r"(r) : "r"(a), "r"(rank));
    return r;
}
__device__ __forceinline__ void mbar_init(unsigned a, unsigned cnt) {
    asm volatile("mbarrier.init.shared.b64 [%0], %1;" :: "r"(a), "r"(cnt) : "memory");
}
__device__ __forceinline__ void mbar_expect(unsigned a, unsigned bytes) {
    asm volatile("mbarrier.arrive.expect_tx.shared.b64 _, [%0], %1;"
                 :: "r"(a), "r"(bytes) : "memory");
}
__device__ __forceinline__ void mbar_wait(unsigned a, unsigned par) {
    unsigned done;
    asm volatile(
        "{\n\t.reg .pred p;\n\t"
        "mbarrier.try_wait.parity.acquire.cta.shared::cta.b64 p, [%1], %2;\n\t"
        "selp.b32 %0, 1, 0, p;\n\t}"
        : "=r"(done) : "r"(a), "r"(par) : "memory");
    if (!done) {
        asm volatile(
            "{\n\t.reg .pred P1;\n"
            "WAIT_%=:\n\t"
            "mbarrier.try_wait.parity.acquire.cta.shared::cta.b64 P1, [%0], %1, 0x989680;\n\t"
            "@P1 bra DONE_%=;\n\t"
            "bra WAIT_%=;\n"
            "DONE_%=:\n\t}"
            :: "r"(a), "r"(par) : "memory");
    }
}
__device__ __forceinline__ void bulk_copy_cluster(unsigned dst, unsigned src,
                                                  unsigned bytes, unsigned rbar) {
    asm volatile(
        "cp.async.bulk.shared::cluster.shared::cta.mbarrier::complete_tx::bytes "
        "[%0], [%1], %2, [%3];"
        :: "r"(dst), "r"(src), "r"(bytes), "r"(rbar) : "memory");
}
__device__ __forceinline__ void fence_async_() {
    asm volatile("fence.proxy.async.shared::cta;" ::: "memory");
}

// ======================================================================
// Encoder: fused single-chain GRU step. 16 clusters x 8 CTAs, 4 batch.
// tid = u*8 + ks. Thread computes 3 gate rows of unit u over k-slice ks
// (weights in regs), shfl.bfly allreduce across ks lanes (in-warp),
// gate lanes compute gates + STS own chunk; __syncthreads; 7x TMA bulk
// publish (self-skip) with tx-mbarrier; acquire.cta waits.
// ======================================================================
__global__ void __launch_bounds__(TENC, 1) __cluster_dims__(CLUSTER, 1, 1)
enc_kernel(const float* __restrict__ x,
           const float* __restrict__ Wih,
           const float* __restrict__ Whh,
           const float* __restrict__ bih,
           const float* __restrict__ bhh)
{
    // h storage: [buf][chunk(=src rank)][batch][ROWF], data at [2*chunk, 2*chunk+38)
    __shared__ __align__(16) float hbuf[2][CLUSTER][NB][ROWF];  // 14336 B
    __shared__ __align__(16) float xst[2][NB][14];              // 448 B
    __shared__ ull wihs[HC][21];                                // 6384 B
    __shared__ ull mbars[2];

    const int tid = threadIdx.x;
    unsigned rank;
    asm("mov.u32 %0, %%cluster_ctarank;" : "=r"(rank));
    const int bg = (blockIdx.x / CLUSTER) * NB;

    // ---- zero hbuf (both parities, incl. pads) + xst ----
    {
        float* hf = (float*)hbuf;
        for (int i = tid; i < 2 * CLUSTER * NB * ROWF; i += TENC) hf[i] = 0.f;
        float* xf = (float*)xst;
        for (int i = tid; i < 2 * NB * 14; i += TENC) xf[i] = 0.f;
    }
    // ---- wihs: all 3 input-gate rows for this CTA's units ----
    for (int i = tid; i < HC * 21; i += TENC) {
        int gi = i / 21, j = i % 21, g = j / 7, fp = j % 7;
        int uu = (int)rank * HC + gi;
        float a = 0.f, b = 0.f;
        if (uu < HID) {
            a = Wih[(g * HID + uu) * FEAT + 2 * fp];
            if (2 * fp + 1 < FEAT) b = Wih[(g * HID + uu) * FEAT + 2 * fp + 1];
        }
        wihs[gi][j] = pk2(a, b);
    }
    __syncthreads();
    // prime x(0)
    if (tid < NB * FEAT) {
        int b = tid / FEAT, f = tid % FEAT;
        xst[0][b][f] = x[((long)(bg + b) * T_STEPS) * FEAT + f];
    }

    const int u   = tid / KSPLIT;   // 0..37
    const int ks  = tid % KSPLIT;   // 0..7
    const int u_g = (int)rank * HC + u;
    const bool active = u_g < HID;

    // ---- Whh slice into registers: 3 gates x 19 pairs, k = ks*38 + 2kp ----
    ull w[3][KPS];
#pragma unroll
    for (int g = 0; g < 3; g++)
#pragma unroll
        for (int kp = 0; kp < KPS; kp++) {
            int k0 = ks * HC + 2 * kp, k1 = k0 + 1;
            float a = (active && k0 < HID) ? Whh[(g * HID + u_g) * HID + k0] : 0.f;
            float b = (active && k1 < HID) ? Whh[(g * HID + u_g) * HID + k1] : 0.f;
            w[g][kp] = pk2(a, b);
        }
    float brz0 = 0.f, brz1 = 0.f, bin_ = 0.f, bhn_ = 0.f;
    if (active) {
        brz0 = bih[u_g]           + bhh[u_g];
        brz1 = bih[HID + u_g]     + bhh[HID + u_g];
        bin_ = bih[2 * HID + u_g];
        bhn_ = bhh[2 * HID + u_g];
    }

    const int gb = ks >> 1;                       // gate lane's batch
    const bool gate_ok = (ks & 1) == 0;           // 4 gate lanes per unit
    float h_keep = 0.f;

    const unsigned hbase = smem_u32(hbuf);
    const unsigned barb  = smem_u32(mbars);
    if (tid == 0) {
        mbar_init(barb, 1);
        mbar_init(barb + 8, 1);
        mbar_expect(barb, EXPB);
        mbar_expect(barb + 8, EXPB);
    }
    // shfl mask: warp 9 has only lanes 0..15
    const unsigned wmask = (tid < 288) ? 0xffffffffu : 0x0000ffffu;

    __syncthreads();
    cluster_sync_();   // barriers + zeroed hbuf visible cluster-wide

    int par0 = 0, par1 = 0;

    for (int t = 0; t < T_STEPS; t++) {
        const int p = t & 1;
        const int buf = p ^ 1;

        // x prefetch for t+1 (LDG before wait: fully hidden)
        float xv = 0.f;
        int xb = 0, xf = 0;
        if (tid < NB * FEAT && t + 1 < T_STEPS) {
            xb = tid / FEAT; xf = tid % FEAT;
            xv = __ldg(&x[((long)(bg + xb) * T_STEPS + t + 1) * FEAT + xf]);
        }

        if (t) {
            const unsigned bw = barb + (unsigned)p * 8u;
            mbar_wait(bw, p ? (unsigned)par1 : (unsigned)par0);
            if (p) par1 ^= 1; else par0 ^= 1;
            if (tid == 0) mbar_expect(bw, EXPB);
        }

        // ---- fused GEMM: 3 gates x 4 batches over this lane's k slice ----
        ull acc[NB][3];
#pragma unroll
        for (int b = 0; b < NB; b++)
#pragma unroll
            for (int g = 0; g < 3; g++) acc[b][g] = 0ull;
        {
            // chunk ks, batch b row: float offset = (ks*4+b)*ROWF + 2*ks
            const ull* r0 = (const ull*)hbuf + ((size_t)p * CLUSTER * NB * ROWF
                             + ks * CHUNKF + 2 * ks) / 2;
#pragma unroll
            for (int kp = 0; kp < KPS; kp++) {
                ull h0 = r0[kp];
                ull h1 = r0[kp + ROWF / 2];
                ull h2 = r0[kp + ROWF];
                ull h3 = r0[kp + 3 * ROWF / 2];
                fma2(acc[0][0], w[0][kp], h0);
                fma2(acc[0][1], w[1][kp], h0);
                fma2(acc[0][2], w[2][kp], h0);
                fma2(acc[1][0], w[0][kp], h1);
                fma2(acc[1][1], w[1][kp], h1);
                fma2(acc[1][2], w[2][kp], h1);
                fma2(acc[2][0], w[0][kp], h2);
                fma2(acc[2][1], w[1][kp], h2);
                fma2(acc[2][2], w[2][kp], h2);
                fma2(acc[3][0], w[0][kp], h3);
                fma2(acc[3][1], w[1][kp], h3);
                fma2(acc[3][2], w[2][kp], h3);
            }
        }
        // ---- in-warp allreduce over ks lanes (xor 1,2,4 on lane) ----
        float s[NB][3];
#pragma unroll
        for (int b = 0; b < NB; b++)
#pragma unroll
            for (int g = 0; g < 3; g++) s[b][g] = upks(acc[b][g]);
#pragma unroll
        for (int d = 1; d < KSPLIT; d <<= 1)
#pragma unroll
            for (int b = 0; b < NB; b++)
#pragma unroll
                for (int g = 0; g < 3; g++)
                    s[b][g] += __shfl_xor_sync(wmask, s[b][g], d);

        // ---- gates (lanes ks even; batch gb = ks>>1) ----
        if (gate_ok) {
            ull d0 = 0, d1 = 0, d2 = 0;
            const ull* xq = (const ull*)&xst[p][gb][0];
#pragma unroll
            for (int fp = 0; fp < 7; fp++) {
                ull xval = xq[fp];
                fma2(d0, wihs[u][fp],      xval);
                fma2(d1, wihs[u][7 + fp],  xval);
                fma2(d2, wihs[u][14 + fp], xval);
            }
            const float r = sig_f(upks(d0) + s[gb][0] + brz0);
            const float z = sig_f(upks(d1) + s[gb][1] + brz1);
            const float n = tanh_f(upks(d2) + bin_ + r * (s[gb][2] + bhn_));
            const float hn = (1.f - z) * n + z * h_keep;
            h_keep = hn;
            // write own chunk slot (float idx: buf, chunk=rank, batch=gb, 2*rank+u)
            ((float*)hbuf)[(((size_t)buf * CLUSTER + rank) * NB + gb) * ROWF
                           + 2 * rank + u] = hn;
        }
        // stage x(t+1)
        if (tid < NB * FEAT && t + 1 < T_STEPS) xst[buf][xb][xf] = xv;

        __syncthreads();

        // ---- publish: 7 TMA bulk copies (self-skip), single tx each ----
        if (t + 1 < T_STEPS && tid < CLUSTER && tid != (int)rank) {
            fence_async_();
            const unsigned src = hbase
                + (unsigned)((buf * CLUSTER + (int)rank) * CHUNKB);
            const unsigned rb = barb + (unsigned)buf * 8u;
            bulk_copy_cluster(mapa_(src, tid), src, CHUNKB, mapa_(rb, tid));
        }
    }

    if (gate_ok && active) g_hlast[(bg + gb) * HID + u_g] = h_keep;

    // no CTA may exit while sibling TMA copies into it may be in flight
    cluster_sync_();
}

// ======================================================================
// fc + relu
// ======================================================================
__global__ void __launch_bounds__(128) fc_kernel(
    const float* __restrict__ fcW, const float* __restrict__ fcb,
    float* __restrict__ dout, int write_emb)
{
    __shared__ float hs[HID];
    const int b = blockIdx.x;
    const int tid = threadIdx.x;
    for (int k = tid; k < HID; k += 128) hs[k] = g_hlast[b * HID + k];
    __syncthreads();
    for (int j = tid; j < HID; j += 128) {
        float a = fcb[j];
        const float* w = fcW + j * HID;
#pragma unroll 4
        for (int k = 0; k < HID; k++) a = fmaf(w[k], hs[k], a);
        a = fmaxf(a, 0.f);
        g_emb[b * HID + j] = a;
        if (write_emb) dout[OUT_EMB_OFF + b * HID + j] = a;
    }
}

// ======================================================================
// Decoder: one warp per batch element, h broadcast via shfl.
// ======================================================================
__global__ void __launch_bounds__(32) dec_kernel(
    const float* __restrict__ dWih, const float* __restrict__ dWhh,
    const float* __restrict__ dbih, const float* __restrict__ dbhh,
    float* __restrict__ out)
{
    const int b = blockIdx.x;
    const int lane = threadIdx.x;

    float wr[FEAT], wz[FEAT], wn[FEAT];
    float gr0 = 0.f, gz0 = 0.f, gn0 = 0.f, bhn = 0.f, h = 0.f;

    if (lane < FEAT) {
        gr0 = dbih[lane]            + dbhh[lane];
        gz0 = dbih[FEAT + lane]     + dbhh[FEAT + lane];
        gn0 = dbih[2 * FEAT + lane];
        bhn = dbhh[2 * FEAT + lane];
        const float* e  = g_emb + b * HID;
        const float* w0 = dWih + lane * HID;
        const float* w1 = dWih + (FEAT + lane) * HID;
        const float* w2 = dWih + (2 * FEAT + lane) * HID;
#pragma unroll 4
        for (int k = 0; k < HID; k++) {
            float ev = e[k];
            gr0 = fmaf(w0[k], ev, gr0);
            gz0 = fmaf(w1[k], ev, gz0);
            gn0 = fmaf(w2[k], ev, gn0);
        }
#pragma unroll
        for (int k = 0; k < FEAT; k++) {
            wr[k] = dWhh[lane * FEAT + k];
            wz[k] = dWhh[(FEAT + lane) * FEAT + k];
            wn[k] = dWhh[(2 * FEAT + lane) * FEAT + k];
        }
    }

    float* ob = out + (long)b * T_STEPS * FEAT;
    for (int t = 0; t < T_STEPS; t++) {
        float sr = 0.f, sz = 0.f, sn = 0.f;
#pragma unroll
        for (int k = 0; k < FEAT; k++) {
            float hk = __shfl_sync(0xffffffffu, h, k);
            sr = fmaf(wr[k], hk, sr);
            sz = fmaf(wz[k], hk, sz);
            sn = fmaf(wn[k], hk, sn);
        }
        if (lane < FEAT) {
            float r = sig_f(gr0 + sr);
            float z = sig_f(gz0 + sz);
            float n = tanh_f(gn0 + r * (sn + bhn));
            h = (1.f - z) * n + z * h;
            ob[t * FEAT + lane] = h;
        }
    }
}

// ======================================================================
// launch
// ======================================================================
extern "C" void kernel_launch(void* const* d_in, const int* in_sizes, int n_in,
                              void* d_out, int out_size)
{
    const float* x        = (const float*)d_in[0];
    const float* enc_Wih  = (const float*)d_in[1];
    const float* enc_Whh  = (const float*)d_in[2];
    const float* enc_bih  = (const float*)d_in[3];
    const float* enc_bhh  = (const float*)d_in[4];
    const float* fc_W     = (const float*)d_in[5];
    const float* fc_b     = (const float*)d_in[6];
    const float* dec_Wih  = (const float*)d_in[7];
    const float* dec_Whh  = (const float*)d_in[8];
    const float* dec_bih  = (const float*)d_in[9];
    const float* dec_bhh  = (const float*)d_in[10];
    float* out = (float*)d_out;

    const int write_emb = (out_size >= OUT_MAIN + BATCH * HID) ? 1 : 0;

    enc_kernel<<<(BATCH / NB) * CLUSTER, TENC>>>(
        x, enc_Wih, enc_Whh, enc_bih, enc_bhh);
    fc_kernel<<<BATCH, 128>>>(fc_W, fc_b, out, write_emb);
    dec_kernel<<<BATCH, 32>>>(dec_Wih, dec_Whh, dec_bih, dec_bhh, out);
}